// round 13
// baseline (speedup 1.0000x reference)
#include <cuda_runtime.h>
#include <cstdint>
#include <float.h>

#define BATCH 16
#define HH 96
#define WW 320
#define HWSZ (HH*WW)      // 30720
#define KTOP 100
#define NMAPS 12          // 3 hm + 9 hm_hp
#define THRESH 0.1f

#define T1 352            // 11 column-warps, one band of 48 rows
#define NW 11
#define WSURV 256         // survivor slots per warp (power of 2)
#define NHIST 8192

typedef unsigned long long u64;

// ---------------- scratch (no cudaMalloc allowed) ----------------
__device__ u64    g_bkeys[BATCH*NMAPS*2*KTOP];   // per-band sorted top-100 keys
__device__ int    g_find  [BATCH*KTOP];
__device__ float4 g_bbox  [BATCH*KTOP];
__device__ float2 g_xy0   [BATCH*KTOP];

__device__ __forceinline__ float sigmoidf_(float x){ return 1.0f/(1.0f + expf(-x)); }

// sortable uint from float bits (monotone, handles negatives)
__device__ __forceinline__ unsigned fsort(float f){
    unsigned u = __float_as_uint(f);
    return u ^ (((unsigned)((int)u >> 31)) | 0x80000000u);
}
__device__ __forceinline__ float funsort(unsigned us){
    unsigned u = (us & 0x80000000u) ? (us ^ 0x80000000u) : ~us;
    return __uint_as_float(u);
}

// =====================================================================
// Kernel 1: per-(map,band) streaming RAW 3x3 NMS + band top-100
//   384 CTAs x 352 thr (3/SM); 4-deep scalar prefetch; per-warp
//   survivor buffers; sigmoid only on ~O(100) candidates
// =====================================================================
__global__ __launch_bounds__(T1, 3)
void topk_map_kernel(const float* __restrict__ hm, const float* __restrict__ hm_hp){
    int mblk = blockIdx.x >> 1;      // b*NMAPS + map
    int q    = blockIdx.x & 1;       // band
    int b    = mblk / NMAPS;
    int map  = mblk - b*NMAPS;
    const float* src = (map < 3) ? (hm    + (size_t)(b*3 +  map     )*HWSZ)
                                 : (hm_hp + (size_t)(b*9 + (map - 3))*HWSZ);

    extern __shared__ char smraw[];
    u64* s_surv = (u64*)smraw;                        // 11*256*8 = 22528
    int* s_hist = (int*)(smraw + 22528);              // 8192*4 = 32768
    u64* s_key  = (u64*)(smraw + 55296);              // 512*8  = 4096
    int* s_part = (int*)(smraw + 59392);              // 256*4  = 1024
    int* s_wcnt = (int*)(smraw + 60416);              // 11*4
    __shared__ int s_ccnt, s_thresh;

    int tid  = threadIdx.x;
    int warp = tid >> 5;
    int lane = tid & 31;
    int x    = 30*warp + lane - 1;   // -1 .. 330
    bool inx = (x >= 0) && (x < WW);
    bool owner = (lane >= 1) && (lane <= 30) && (x < WW);
    int ybase = q*48 - 1;            // first (halo) row

    {   // fast hist zero (uint4)
        uint4* h4 = (uint4*)s_hist;
        for (int i = tid; i < NHIST/4; i += T1) h4[i] = make_uint4(0,0,0,0);
    }
    if (tid < NW) s_wcnt[tid] = 0;
    if (tid == 0){ s_ccnt = 0; s_thresh = 0; }

    const float NEG = -FLT_MAX;
    const float* colp = src + x;     // column base (valid only if inx)
    int* mycnt = &s_wcnt[warp];
    u64* mybuf = &s_surv[warp << 8]; // warp region, WSURV=256

    // prime 4-stage scalar pipeline with rows ybase..ybase+3
    float pf0 = (inx && ybase+0 >= 0) ? __ldg(colp + (ybase+0)*WW) : NEG;
    float pf1 =  inx                  ? __ldg(colp + (ybase+1)*WW) : NEG;
    float pf2 =  inx                  ? __ldg(colp + (ybase+2)*WW) : NEG;
    float pf3 =  inx                  ? __ldg(colp + (ybase+3)*WW) : NEG;

    float h1 = NEG, h0 = NEG, s_prev = NEG;

    __syncthreads();   // hist/wcnt ready before any emit

#define STEP(PFREG, YY_)                                                     \
    {                                                                        \
        const int yy = (YY_);                                                \
        float s = (yy < 50) ? (PFREG) : NEG;                                 \
        if (yy + 4 < 50){                                                    \
            int rn = ybase + yy + 4;                                         \
            PFREG = (inx && rn < HH) ? __ldg(colp + rn*WW) : NEG;            \
        }                                                                    \
        float lv = __shfl_up_sync(0xffffffffu, s, 1);                        \
        float rv = __shfl_down_sync(0xffffffffu, s, 1);                      \
        float h  = fmaxf(fmaxf(lv, rv), s);                                  \
        if (yy >= 2 && yy < 50 && owner){   /* emit rows ybase+1..ybase+48 */ \
            float vmax = fmaxf(fmaxf(h1, h0), h);                            \
            bool surv = (vmax == s_prev);                                    \
            if (!surv && (vmax - s_prev) < 1e-4f){                           \
                surv = (__float_as_uint(sigmoidf_(vmax)) ==                  \
                        __float_as_uint(sigmoidf_(s_prev)));                 \
            }                                                                \
            if (surv){                                                       \
                unsigned us = fsort(s_prev);                                 \
                atomicAdd(&s_hist[us >> 19], 1);                             \
                int pos = atomicAdd(mycnt, 1);                               \
                if (pos < WSURV)                                             \
                    mybuf[pos] = ((u64)us << 32) |                           \
                                 (unsigned)(~((ybase + yy - 1)*WW + x));     \
            }                                                                \
        }                                                                    \
        h1 = h0; h0 = h; s_prev = s;                                         \
    }

    for (int yb = 0; yb < 52; yb += 4){
        STEP(pf0, yb+0)
        STEP(pf1, yb+1)
        STEP(pf2, yb+2)
        STEP(pf3, yb+3)
    }
#undef STEP
    __syncthreads();

    // ---- parallel radix-select: chunk partials + prefix scan ----
    int psum = 0;
    if (tid < 256){
        int hi = NHIST - 32*tid;     // covers [hi-32, hi), chunks from top
        #pragma unroll
        for (int i = hi-32; i < hi; i++) psum += s_hist[i];
        s_part[tid] = psum;
    }
    __syncthreads();
    #pragma unroll
    for (int off = 1; off < 256; off <<= 1){
        int v = 0;
        if (tid < 256 && tid >= off) v = s_part[tid - off];
        __syncthreads();
        if (tid < 256) s_part[tid] += v;
        __syncthreads();
    }
    if (tid < 256){
        int incl = s_part[tid];
        int excl = incl - psum;
        if (excl < KTOP && incl >= KTOP){   // exactly one chunk crosses
            int hi2 = NHIST - 32*tid;
            int acc = excl, thr = 0;
            for (int i = hi2-1; i >= hi2-32; i--){
                acc += s_hist[i];
                if (acc >= KTOP){ thr = i; break; }
            }
            s_thresh = (thr > 0) ? thr - 1 : 0;  // one-bucket margin: sigmoid ties
        }
    }
    __syncthreads();

    // collect candidates (raw-bits >= threshold), substituting sigmoid keys
    unsigned ut = (unsigned)s_thresh << 19;
    for (int i = tid; i < NW*WSURV; i += T1){
        int wi = i >> 8, o = i & (WSURV-1);
        if (o < s_wcnt[wi]){
            u64 key = s_surv[i];
            unsigned us = (unsigned)(key >> 32);
            if (us >= ut){
                int pos = atomicAdd(&s_ccnt, 1);
                if (pos < 512){
                    float sig = sigmoidf_(funsort(us));
                    s_key[pos] = ((u64)__float_as_uint(sig) << 32) | (unsigned)key;
                }
            }
        }
    }
    __syncthreads();
    int nc = min(s_ccnt, 512);
    int SS = (nc <= 256) ? 256 : 512;     // dynamic sort size
    for (int i = tid; i < SS; i += T1) if (i >= nc) s_key[i] = 0ULL;
    __syncthreads();

    // bitonic sort descending: (sigmoid desc, index asc)
    for (int kk = 2; kk <= SS; kk <<= 1){
        for (int jj = kk >> 1; jj > 0; jj >>= 1){
            for (int i = tid; i < SS; i += T1){
                int ixj = i ^ jj;
                if (ixj > i){
                    u64 a = s_key[i], c2 = s_key[ixj];
                    bool up = ((i & kk) == 0);
                    if (up ? (a < c2) : (a > c2)){ s_key[i] = c2; s_key[ixj] = a; }
                }
            }
            __syncthreads();
        }
    }

    if (tid < KTOP)
        g_bkeys[(size_t)blockIdx.x*KTOP + tid] = s_key[tid];
}

// =====================================================================
// Kernel 2: per-batch: band-merge 3 hm channels (2x100 each), then
// top-100 over 300, then ALL per-detection gathers
// =====================================================================
__global__ __launch_bounds__(512)
void merge_batch_kernel(const float* __restrict__ wh,  const float* __restrict__ reg,
                        const float* __restrict__ dim, const float* __restrict__ rot,
                        const float* __restrict__ prob, float* __restrict__ out){
    __shared__ u64 sk[1024];
    __shared__ u64 sk2[512];
    __shared__ unsigned spix[300];
    int b = blockIdx.x, tid = threadIdx.x;

    // stage A: compound sort (channel asc, sigmoid desc, pix asc) over 600
    for (int i = tid; i < 1024; i += 512){
        u64 key = 0;
        if (i < 600){
            int c = i / 200, r2 = i - c*200;          // r2 in [0,200): band*100+r
            u64 bk = g_bkeys[(size_t)(((b*NMAPS + c)*2)*KTOP) + r2];
            unsigned sig = (unsigned)(bk >> 32);
            unsigned pix = ~(unsigned)bk;             // < 30720 < 2^15
            key = ((u64)(3 - c) << 47) | ((u64)sig << 15)
                | (u64)((pix ^ 0x7FFFu) & 0x7FFFu);
        }
        sk[i] = key;
    }
    __syncthreads();
    for (int kk = 2; kk <= 1024; kk <<= 1){
        for (int jj = kk >> 1; jj > 0; jj >>= 1){
            for (int i = tid; i < 1024; i += 512){
                int ixj = i ^ jj;
                if (ixj > i){
                    u64 a = sk[i], c2 = sk[ixj];
                    bool up = ((i & kk) == 0);
                    if (up ? (a < c2) : (a > c2)){ sk[i] = c2; sk[ixj] = a; }
                }
            }
            __syncthreads();
        }
    }
    // stage B: flat-rank keys over the 3x100 channel tops
    if (tid < 512){
        u64 key2 = 0;
        if (tid < 300){
            int c = tid / 100, r = tid - c*100;
            u64 key = sk[c*200 + r];                  // channel c sorted block
            unsigned sig = (unsigned)((key >> 15) & 0xFFFFFFFFull);
            unsigned pix = ((unsigned)key & 0x7FFFu) ^ 0x7FFFu;
            spix[tid] = pix;
            key2 = ((u64)sig << 32) | (unsigned)(~(unsigned)tid);
        }
        sk2[tid] = key2;
    }
    __syncthreads();
    for (int kk = 2; kk <= 512; kk <<= 1){
        for (int jj = kk >> 1; jj > 0; jj >>= 1){
            int i = tid, ixj = tid ^ jj;
            if (ixj > i){
                u64 a = sk2[i], c2 = sk2[ixj];
                bool up = ((i & kk) == 0);
                if (up ? (a < c2) : (a > c2)){ sk2[i] = c2; sk2[ixj] = a; }
            }
            __syncthreads();
        }
    }
    if (tid < KTOP){
        u64 key = sk2[tid];
        float sc = __uint_as_float((unsigned)(key >> 32));
        unsigned flat = ~(unsigned)key;
        int cls = flat / 100;
        int ind = (int)spix[flat];
        g_find[b*KTOP + tid] = ind;

        float x0 = (float)(ind % WW);
        float y0 = (float)(ind / WW);
        float rx = reg[((size_t)b*2 + 0)*HWSZ + ind];
        float ry = reg[((size_t)b*2 + 1)*HWSZ + ind];
        float xs = x0 + rx, ys = y0 + ry;
        float w0 = wh[((size_t)b*2 + 0)*HWSZ + ind];
        float w1 = wh[((size_t)b*2 + 1)*HWSZ + ind];
        float l  = xs - w0*0.5f, tt = ys - w1*0.5f;
        float r  = xs + w0*0.5f, bo = ys + w1*0.5f;
        g_bbox[b*KTOP + tid] = make_float4(l, tt, r, bo);
        g_xy0 [b*KTOP + tid] = make_float2(x0, y0);

        float* det = out + ((size_t)b*KTOP + tid)*45;
        det[0] = l*4.0f; det[1] = tt*4.0f; det[2] = r*4.0f; det[3] = bo*4.0f;
        det[4] = sc;
        det[23] = dim[((size_t)b*3 + 0)*HWSZ + ind];
        det[24] = dim[((size_t)b*3 + 1)*HWSZ + ind];
        det[25] = dim[((size_t)b*3 + 2)*HWSZ + ind];
        #pragma unroll
        for (int c = 0; c < 8; c++)
            det[35 + c] = rot[((size_t)b*8 + c)*HWSZ + ind];
        det[43] = prob[(size_t)b*HWSZ + ind];
        det[44] = (float)cls;
    }
}

// =====================================================================
// Kernel 3: 144 CTAs (9 joints x 16 batches): band-merge channel 3+j,
// then keypoint matching (squared-distance argmin, exact tie pass)
// =====================================================================
__global__ __launch_bounds__(128)
void decode_kernel(const float* __restrict__ hps,
                   const float* __restrict__ hp_offset, float* __restrict__ out){
    int j = blockIdx.x;
    int b = blockIdx.y;
    int tid = threadIdx.x;

    __shared__ u64 sk[256];
    __shared__ float hmx[100], hmy[100], hmsc[100];
    __shared__ float bl[100], bt[100], br[100], bbm[100];
    __shared__ float kx[100], ky[100];

    // band-merge: 2x100 sorted band keys -> global channel top-100
    size_t base = (size_t)(((b*NMAPS + 3 + j)*2)*KTOP);
    for (int i = tid; i < 256; i += 128)
        sk[i] = (i < 200) ? g_bkeys[base + i] : 0ULL;
    __syncthreads();
    for (int kk = 2; kk <= 256; kk <<= 1){
        for (int jj = kk >> 1; jj > 0; jj >>= 1){
            for (int i = tid; i < 256; i += 128){
                int ixj = i ^ jj;
                if (ixj > i){
                    u64 a = sk[i], c2 = sk[ixj];
                    bool up = ((i & kk) == 0);
                    if (up ? (a < c2) : (a > c2)){ sk[i] = c2; sk[ixj] = a; }
                }
            }
            __syncthreads();
        }
    }

    if (tid < KTOP){
        int k = tid;
        u64 key = sk[k];
        float sc = __uint_as_float((unsigned)(key >> 32));
        int ind  = (int)(~(unsigned)key);
        int ind2 = g_find[b*KTOP + k];
        float ox = hp_offset[((size_t)b*2 + 0)*HWSZ + ind];
        float oy = hp_offset[((size_t)b*2 + 1)*HWSZ + ind];
        float hx0 = hps[((size_t)b*18 + 2*j    )*HWSZ + ind2];
        float hy0 = hps[((size_t)b*18 + 2*j + 1)*HWSZ + ind2];
        float4 bb = g_bbox[b*KTOP + k];
        float2 xy = g_xy0 [b*KTOP + k];

        float xq = (float)(ind % WW) + ox;
        float yq = (float)(ind / WW) + oy;
        bool valid = sc > THRESH;
        hmsc[k] = valid ? sc : -1.0f;
        hmx [k] = valid ? xq : -10000.0f;
        hmy [k] = valid ? yq : -10000.0f;

        bl[k] = bb.x; bt[k] = bb.y; br[k] = bb.z; bbm[k] = bb.w;
        kx[k] = hx0 + xy.x;
        ky[k] = hy0 + xy.y;
    }
    __syncthreads();

    if (tid < KTOP){
        int k = tid;
        float px = kx[k], py = ky[k];
        float bsq = FLT_MAX; int bm = 0;
        #pragma unroll 4
        for (int mm = 0; mm < 100; mm++){
            float dx = px - hmx[mm];
            float dy = py - hmy[mm];
            float sq = dx*dx + dy*dy;
            if (sq < bsq){ bsq = sq; bm = mm; }
        }
        float smin = sqrtf(bsq);
        float lim = bsq * 1.000001f;   // sqrt rounding collapse window
        for (int mm = 0; mm < bm; mm++){
            float dx = px - hmx[mm];
            float dy = py - hmy[mm];
            float sq = dx*dx + dy*dy;
            if (sq <= lim && sqrtf(sq) == smin){ bm = mm; break; }
        }
        float hs = hmsc[bm], hx = hmx[bm], hy = hmy[bm];
        float l = bl[k], tt = bt[k], r = br[k], bo = bbm[k];
        bool invalid = (hx < l) || (hx > r) || (hy < tt) || (hy > bo) ||
                       (hs < THRESH) ||
                       (smin > fmaxf(bo - tt, r - l)*0.3f);
        float fx = invalid ? px : hx;
        float fy = invalid ? py : hy;
        float* det = out + ((size_t)b*KTOP + k)*45;
        det[5 + 2*j] = fx*4.0f;
        det[6 + 2*j] = fy*4.0f;
        det[26 + j]  = hs;
    }
}

// =====================================================================
extern "C" void kernel_launch(void* const* d_in, const int* in_sizes, int n_in,
                              void* d_out, int out_size){
    const float* hm        = (const float*)d_in[0];
    const float* wh        = (const float*)d_in[1];
    const float* hps       = (const float*)d_in[2];
    const float* dim       = (const float*)d_in[3];
    const float* rot       = (const float*)d_in[4];
    const float* prob      = (const float*)d_in[5];
    const float* reg       = (const float*)d_in[6];
    const float* hm_hp     = (const float*)d_in[7];
    const float* hp_offset = (const float*)d_in[8];
    float* out = (float*)d_out;

    const int SMEM1 = 22528 + 32768 + 4096 + 1024 + 64;   // 60480 B
    cudaFuncSetAttribute(topk_map_kernel,
                         cudaFuncAttributeMaxDynamicSharedMemorySize, SMEM1);

    topk_map_kernel<<<BATCH*NMAPS*2, T1, SMEM1>>>(hm, hm_hp);
    merge_batch_kernel<<<BATCH, 512>>>(wh, reg, dim, rot, prob, out);
    decode_kernel<<<dim3(9, BATCH), 128>>>(hps, hp_offset, out);
}

// round 14
// speedup vs baseline: 1.3927x; 1.3927x over previous
#include <cuda_runtime.h>
#include <cstdint>
#include <float.h>

#define BATCH 16
#define HH 96
#define WW 320
#define HWSZ (HH*WW)      // 30720
#define KTOP 100
#define NMAPS 12          // 3 hm + 9 hm_hp
#define THRESH 0.1f

#define T1 704            // 22 warps: 2 row-bands x 11 column-warps
#define NW 22
#define WSURV 256         // survivor slots per warp (power of 2)
#define NHIST 8192
#define NTAIL 160         // 10 jobs x 16 batches

typedef unsigned long long u64;

// ---------------- scratch (no cudaMalloc allowed) ----------------
__device__ float    g_scores[BATCH*NMAPS*KTOP];
__device__ int      g_inds  [BATCH*NMAPS*KTOP];
__device__ unsigned g_done  = 0;   // phase-1 completion counter
__device__ unsigned g_done2 = 0;   // tail completion counter (for reset)

__device__ __forceinline__ float sigmoidf_(float x){ return 1.0f/(1.0f + expf(-x)); }

// sortable uint from float bits (monotone, handles negatives)
__device__ __forceinline__ unsigned fsort(float f){
    unsigned u = __float_as_uint(f);
    return u ^ (((unsigned)((int)u >> 31)) | 0x80000000u);
}
__device__ __forceinline__ float funsort(unsigned us){
    unsigned u = (us & 0x80000000u) ? (us ^ 0x80000000u) : ~us;
    return __uint_as_float(u);
}

// =====================================================================
// ONE persistent kernel.
// Phase 1 (192 CTAs): per-(batch,channel) streaming RAW 3x3 NMS +
//   top-100 (2 row-bands x 11 col-warps, 4-deep scalar prefetch,
//   per-warp survivor buffers, radix-select + bitonic).
// Global barrier (all 192 CTAs resident in one wave).
// Phase 2 (CTAs 0..159): rank-merge 300->100 (binary search, 2 barriers)
//   + per-detection gathers (job 9) / joint matching (jobs 0..8).
// =====================================================================
__global__ __launch_bounds__(T1, 2)
void km3d_kernel(const float* __restrict__ hm,  const float* __restrict__ hm_hp,
                 const float* __restrict__ wh,  const float* __restrict__ hps,
                 const float* __restrict__ dim, const float* __restrict__ rot,
                 const float* __restrict__ prob,const float* __restrict__ reg,
                 const float* __restrict__ hp_offset, float* __restrict__ out){
    int blk = blockIdx.x;            // phase 1: b*NMAPS + map
    int b   = blk / NMAPS;
    int map = blk - b*NMAPS;
    const float* src = (map < 3) ? (hm    + (size_t)(b*3 +  map     )*HWSZ)
                                 : (hm_hp + (size_t)(b*9 + (map - 3))*HWSZ);

    extern __shared__ char smraw[];
    u64* s_surv = (u64*)smraw;                        // NW*WSURV*8 = 45056
    int* s_hist = (int*)(smraw + 45056);              // 8192*4 = 32768
    u64* s_key  = (u64*)(smraw + 77824);              // 512*8  = 4096
    int* s_part = (int*)(smraw + 81920);              // 256*4  = 1024
    int* s_wcnt = (int*)(smraw + 82944);              // 22*4
    __shared__ int s_ccnt, s_thresh;

    int tid  = threadIdx.x;
    int warp = tid >> 5;
    int lane = tid & 31;
    int g    = warp / 11;            // row band 0/1
    int w    = warp - 11*g;          // column warp
    int x    = 30*w + lane - 1;      // -1 .. 330
    bool inx = (x >= 0) && (x < WW);
    bool owner = (lane >= 1) && (lane <= 30) && (x < WW);
    int ybase = g*48 - 1;            // first (halo) row

    {   // fast hist zero (uint4)
        uint4* h4 = (uint4*)s_hist;
        for (int i = tid; i < NHIST/4; i += T1) h4[i] = make_uint4(0,0,0,0);
    }
    if (tid < NW) s_wcnt[tid] = 0;
    if (tid == 0){ s_ccnt = 0; s_thresh = 0; }

    const float NEG = -FLT_MAX;
    const float* colp = src + x;
    int* mycnt = &s_wcnt[warp];
    u64* mybuf = &s_surv[warp << 8];

    // prime 4-stage scalar pipeline with rows ybase..ybase+3
    float pf0 = (inx && ybase+0 >= 0) ? __ldg(colp + (ybase+0)*WW) : NEG;
    float pf1 =  inx                  ? __ldg(colp + (ybase+1)*WW) : NEG;
    float pf2 =  inx                  ? __ldg(colp + (ybase+2)*WW) : NEG;
    float pf3 =  inx                  ? __ldg(colp + (ybase+3)*WW) : NEG;

    float h1 = NEG, h0 = NEG, s_prev = NEG;

    __syncthreads();   // hist/wcnt ready before any emit

#define STEP(PFREG, YY_)                                                     \
    {                                                                        \
        const int yy = (YY_);                                                \
        float s = (yy < 50) ? (PFREG) : NEG;                                 \
        if (yy + 4 < 50){                                                    \
            int rn = ybase + yy + 4;                                         \
            PFREG = (inx && rn < HH) ? __ldg(colp + rn*WW) : NEG;            \
        }                                                                    \
        float lv = __shfl_up_sync(0xffffffffu, s, 1);                        \
        float rv = __shfl_down_sync(0xffffffffu, s, 1);                      \
        float h  = fmaxf(fmaxf(lv, rv), s);                                  \
        if (yy >= 2 && yy < 50 && owner){   /* emit rows ybase+1..ybase+48 */ \
            float vmax = fmaxf(fmaxf(h1, h0), h);                            \
            bool surv = (vmax == s_prev);                                    \
            if (!surv && (vmax - s_prev) < 1e-4f){                           \
                surv = (__float_as_uint(sigmoidf_(vmax)) ==                  \
                        __float_as_uint(sigmoidf_(s_prev)));                 \
            }                                                                \
            if (surv){                                                       \
                unsigned us = fsort(s_prev);                                 \
                atomicAdd(&s_hist[us >> 19], 1);                             \
                int pos = atomicAdd(mycnt, 1);                               \
                if (pos < WSURV)                                             \
                    mybuf[pos] = ((u64)us << 32) |                           \
                                 (unsigned)(~((ybase + yy - 1)*WW + x));     \
            }                                                                \
        }                                                                    \
        h1 = h0; h0 = h; s_prev = s;                                         \
    }

    for (int yb = 0; yb < 52; yb += 4){
        STEP(pf0, yb+0)
        STEP(pf1, yb+1)
        STEP(pf2, yb+2)
        STEP(pf3, yb+3)
    }
#undef STEP
    __syncthreads();

    // ---- parallel radix-select: chunk partials + prefix scan ----
    int psum = 0;
    if (tid < 256){
        int hi = NHIST - 32*tid;
        #pragma unroll
        for (int i = hi-32; i < hi; i++) psum += s_hist[i];
        s_part[tid] = psum;
    }
    __syncthreads();
    #pragma unroll
    for (int off = 1; off < 256; off <<= 1){
        int v = 0;
        if (tid < 256 && tid >= off) v = s_part[tid - off];
        __syncthreads();
        if (tid < 256) s_part[tid] += v;
        __syncthreads();
    }
    if (tid < 256){
        int incl = s_part[tid];
        int excl = incl - psum;
        if (excl < KTOP && incl >= KTOP){
            int hi2 = NHIST - 32*tid;
            int acc = excl, thr = 0;
            for (int i = hi2-1; i >= hi2-32; i--){
                acc += s_hist[i];
                if (acc >= KTOP){ thr = i; break; }
            }
            s_thresh = (thr > 0) ? thr - 1 : 0;   // sigmoid-tie margin
        }
    }
    __syncthreads();

    // collect candidates, substituting sigmoid keys
    unsigned ut = (unsigned)s_thresh << 19;
    for (int i = tid; i < NW*WSURV; i += T1){
        int wi = i >> 8, o = i & (WSURV-1);
        if (o < s_wcnt[wi]){
            u64 key = s_surv[i];
            unsigned us = (unsigned)(key >> 32);
            if (us >= ut){
                int pos = atomicAdd(&s_ccnt, 1);
                if (pos < 512){
                    float sig = sigmoidf_(funsort(us));
                    s_key[pos] = ((u64)__float_as_uint(sig) << 32) | (unsigned)key;
                }
            }
        }
    }
    __syncthreads();
    int nc = min(s_ccnt, 512);
    int SS = (nc <= 256) ? 256 : 512;
    for (int i = tid; i < SS; i += T1) if (i >= nc) s_key[i] = 0ULL;
    __syncthreads();

    for (int kk = 2; kk <= SS; kk <<= 1){
        for (int jj = kk >> 1; jj > 0; jj >>= 1){
            for (int i = tid; i < SS; i += T1){
                int ixj = i ^ jj;
                if (ixj > i){
                    u64 a = s_key[i], c2 = s_key[ixj];
                    bool up = ((i & kk) == 0);
                    if (up ? (a < c2) : (a > c2)){ s_key[i] = c2; s_key[ixj] = a; }
                }
            }
            __syncthreads();
        }
    }

    if (tid < KTOP){
        u64 key = s_key[tid];
        g_scores[blk*KTOP + tid] = __uint_as_float((unsigned)(key >> 32));
        g_inds  [blk*KTOP + tid] = (int)(~(unsigned)key);
    }

    // ================= global barrier (all 192 CTAs resident) ==========
    __threadfence();
    __syncthreads();
    if (tid == 0) atomicAdd(&g_done, 1u);
    if (blk >= NTAIL) return;                      // CTAs 160..191 done
    if (tid == 0){
        while (*((volatile unsigned*)&g_done) < (unsigned)(BATCH*NMAPS)) {}
        __threadfence();
    }
    __syncthreads();

    // ================= phase 2: tail ===================================
    int b2  = blk & 15;
    int job = blk >> 4;                            // 0..9

    u64*   ck  = (u64*)  smraw;                    // 300 keys   (2400 B)
    float* sfs = (float*)(smraw + 2400);           // 100
    int*   sfi = (int*)  (smraw + 2800);           // 100
    int*   sfc = (int*)  (smraw + 3200);           // 100
    float* hmx = (float*)(smraw + 3600);
    float* hmy = (float*)(smraw + 4000);
    float* hmsc= (float*)(smraw + 4400);
    float* bl  = (float*)(smraw + 4800);
    float* bt  = (float*)(smraw + 5200);
    float* br  = (float*)(smraw + 5600);
    float* bbm = (float*)(smraw + 6000);
    float* kx  = (float*)(smraw + 6400);
    float* ky  = (float*)(smraw + 6800);

    // ---- rank merge: 3 sorted channel lists -> global top-100 ----
    if (tid < 300){
        int c = tid / 100, r = tid - c*100;
        float v = g_scores[(b2*NMAPS + c)*KTOP + r];
        ck[tid] = ((u64)__float_as_uint(v) << 32) | (unsigned)(~(unsigned)tid);
        (void)r;
    }
    __syncthreads();
    if (tid < 300){
        int c = tid / 100, r = tid - c*100;
        u64 me = ck[tid];
        int rank = r;
        #pragma unroll
        for (int c2 = 0; c2 < 3; c2++){
            if (c2 == c) continue;
            int lo = 0, hi2 = 100;
            while (lo < hi2){
                int mid = (lo + hi2) >> 1;
                if (ck[c2*100 + mid] > me) lo = mid + 1; else hi2 = mid;
            }
            rank += lo;
        }
        if (rank < KTOP){
            sfs[rank] = __uint_as_float((unsigned)(me >> 32));
            sfc[rank] = c;
            sfi[rank] = g_inds[(b2*NMAPS + c)*KTOP + r];
        }
    }
    __syncthreads();

    if (job == 9){
        // per-detection scalar fields
        if (tid < KTOP){
            int k = tid;
            int ind = sfi[k];
            float x0 = (float)(ind % WW);
            float y0 = (float)(ind / WW);
            float rx = reg[((size_t)b2*2 + 0)*HWSZ + ind];
            float ry = reg[((size_t)b2*2 + 1)*HWSZ + ind];
            float xs = x0 + rx, ys = y0 + ry;
            float w0 = wh[((size_t)b2*2 + 0)*HWSZ + ind];
            float w1 = wh[((size_t)b2*2 + 1)*HWSZ + ind];
            float* det = out + ((size_t)b2*KTOP + k)*45;
            det[0] = (xs - w0*0.5f)*4.0f;
            det[1] = (ys - w1*0.5f)*4.0f;
            det[2] = (xs + w0*0.5f)*4.0f;
            det[3] = (ys + w1*0.5f)*4.0f;
            det[4] = sfs[k];
            det[23] = dim[((size_t)b2*3 + 0)*HWSZ + ind];
            det[24] = dim[((size_t)b2*3 + 1)*HWSZ + ind];
            det[25] = dim[((size_t)b2*3 + 2)*HWSZ + ind];
            #pragma unroll
            for (int c = 0; c < 8; c++)
                det[35 + c] = rot[((size_t)b2*8 + c)*HWSZ + ind];
            det[43] = prob[(size_t)b2*HWSZ + ind];
            det[44] = (float)sfc[k];
        }
    } else {
        int j = job;
        if (tid < KTOP){
            int k = tid;
            int base = (b2*NMAPS + 3 + j)*KTOP + k;
            int ind  = g_inds[base];
            float sc = g_scores[base];
            int ind2 = sfi[k];
            float ox = hp_offset[((size_t)b2*2 + 0)*HWSZ + ind];
            float oy = hp_offset[((size_t)b2*2 + 1)*HWSZ + ind];
            float rx = reg[((size_t)b2*2 + 0)*HWSZ + ind2];
            float ry = reg[((size_t)b2*2 + 1)*HWSZ + ind2];
            float w0 = wh[((size_t)b2*2 + 0)*HWSZ + ind2];
            float w1 = wh[((size_t)b2*2 + 1)*HWSZ + ind2];
            float hx0 = hps[((size_t)b2*18 + 2*j    )*HWSZ + ind2];
            float hy0 = hps[((size_t)b2*18 + 2*j + 1)*HWSZ + ind2];

            float xq = (float)(ind % WW) + ox;
            float yq = (float)(ind / WW) + oy;
            bool valid = sc > THRESH;
            hmsc[k] = valid ? sc : -1.0f;
            hmx [k] = valid ? xq : -10000.0f;
            hmy [k] = valid ? yq : -10000.0f;

            float x0 = (float)(ind2 % WW);
            float y0 = (float)(ind2 / WW);
            float xs = x0 + rx, ys = y0 + ry;
            bl[k] = xs - w0*0.5f; bt[k]  = ys - w1*0.5f;
            br[k] = xs + w0*0.5f; bbm[k] = ys + w1*0.5f;
            kx[k] = hx0 + x0;
            ky[k] = hy0 + y0;
        }
        __syncthreads();

        if (tid < KTOP){
            int k = tid;
            float px = kx[k], py = ky[k];
            float bsq = FLT_MAX; int bm = 0;
            #pragma unroll 4
            for (int mm = 0; mm < 100; mm++){
                float dx = px - hmx[mm];
                float dy = py - hmy[mm];
                float sq = dx*dx + dy*dy;
                if (sq < bsq){ bsq = sq; bm = mm; }
            }
            float smin = sqrtf(bsq);
            float lim = bsq * 1.000001f;   // sqrt rounding collapse window
            for (int mm = 0; mm < bm; mm++){
                float dx = px - hmx[mm];
                float dy = py - hmy[mm];
                float sq = dx*dx + dy*dy;
                if (sq <= lim && sqrtf(sq) == smin){ bm = mm; break; }
            }
            float hs = hmsc[bm], hx = hmx[bm], hy = hmy[bm];
            float l = bl[k], tt = bt[k], r = br[k], bo = bbm[k];
            bool invalid = (hx < l) || (hx > r) || (hy < tt) || (hy > bo) ||
                           (hs < THRESH) ||
                           (smin > fmaxf(bo - tt, r - l)*0.3f);
            float fx = invalid ? px : hx;
            float fy = invalid ? py : hy;
            float* det = out + ((size_t)b2*KTOP + k)*45;
            det[5 + 2*j] = fx*4.0f;
            det[6 + 2*j] = fy*4.0f;
            det[26 + j]  = hs;
        }
    }

    // ---- counter reset for graph replays (last tail CTA cleans up) ----
    __syncthreads();
    if (tid == 0){
        unsigned d = atomicAdd(&g_done2, 1u);
        if (d == (unsigned)(NTAIL - 1)){
            g_done = 0u;
            __threadfence();
            atomicExch(&g_done2, 0u);
        }
    }
}

// =====================================================================
extern "C" void kernel_launch(void* const* d_in, const int* in_sizes, int n_in,
                              void* d_out, int out_size){
    const float* hm        = (const float*)d_in[0];
    const float* wh        = (const float*)d_in[1];
    const float* hps       = (const float*)d_in[2];
    const float* dim       = (const float*)d_in[3];
    const float* rot       = (const float*)d_in[4];
    const float* prob      = (const float*)d_in[5];
    const float* reg       = (const float*)d_in[6];
    const float* hm_hp     = (const float*)d_in[7];
    const float* hp_offset = (const float*)d_in[8];
    float* out = (float*)d_out;

    const int SMEM1 = 45056 + 32768 + 4096 + 1024 + 128;   // 83072 B
    cudaFuncSetAttribute(km3d_kernel,
                         cudaFuncAttributeMaxDynamicSharedMemorySize, SMEM1);

    km3d_kernel<<<BATCH*NMAPS, T1, SMEM1>>>(hm, hm_hp, wh, hps, dim, rot,
                                            prob, reg, hp_offset, out);
}

// round 15
// speedup vs baseline: 1.4942x; 1.0729x over previous
#include <cuda_runtime.h>
#include <cstdint>
#include <float.h>

#define BATCH 16
#define HH 96
#define WW 320
#define HWSZ (HH*WW)      // 30720
#define KTOP 100
#define NMAPS 12          // 3 hm + 9 hm_hp
#define THRESH 0.1f

#define T1 704            // 22 warps: 2 row-bands x 11 column-warps
#define NW 22
#define WSURV 256         // survivor slots per warp (power of 2)
#define NHIST 8192
#define NTAIL 160         // 10 jobs x 16 batches

typedef unsigned long long u64;

// ---------------- scratch (no cudaMalloc allowed) ----------------
__device__ float    g_scores[BATCH*NMAPS*KTOP];
__device__ int      g_inds  [BATCH*NMAPS*KTOP];
__device__ unsigned g_done  = 0;   // phase-1 completion counter
__device__ unsigned g_done2 = 0;   // tail completion counter (for reset)

__device__ __forceinline__ float sigmoidf_(float x){ return 1.0f/(1.0f + expf(-x)); }

// sortable uint from float bits (monotone, handles negatives)
__device__ __forceinline__ unsigned fsort(float f){
    unsigned u = __float_as_uint(f);
    return u ^ (((unsigned)((int)u >> 31)) | 0x80000000u);
}
__device__ __forceinline__ float funsort(unsigned us){
    unsigned u = (us & 0x80000000u) ? (us ^ 0x80000000u) : ~us;
    return __uint_as_float(u);
}

// =====================================================================
// ONE persistent kernel.
// Phase 1 (192 CTAs): streaming RAW 3x3 NMS + top-100 per map.
//   Epilogue uses shfl prefix-scan + RANK SORT (no bitonic): ~6 barriers.
// Global barrier (all 192 CTAs resident in one wave).
// Phase 2 (CTAs 0..159): rank-merge 300->100 + gathers / joint matching.
// =====================================================================
__global__ __launch_bounds__(T1, 2)
void km3d_kernel(const float* __restrict__ hm,  const float* __restrict__ hm_hp,
                 const float* __restrict__ wh,  const float* __restrict__ hps,
                 const float* __restrict__ dim, const float* __restrict__ rot,
                 const float* __restrict__ prob,const float* __restrict__ reg,
                 const float* __restrict__ hp_offset, float* __restrict__ out){
    int blk = blockIdx.x;            // phase 1: b*NMAPS + map
    int b   = blk / NMAPS;
    int map = blk - b*NMAPS;
    const float* src = (map < 3) ? (hm    + (size_t)(b*3 +  map     )*HWSZ)
                                 : (hm_hp + (size_t)(b*9 + (map - 3))*HWSZ);

    extern __shared__ char smraw[];
    u64* s_surv = (u64*)smraw;                        // NW*WSURV*8 = 45056
    int* s_hist = (int*)(smraw + 45056);              // 8192*4 = 32768
    u64* s_key  = (u64*)(smraw + 77824);              // 512*8  = 4096
    int* s_wcnt = (int*)(smraw + 81920);              // 22*4
    __shared__ int s_ccnt, s_thresh;
    __shared__ int s_wsum[8];

    int tid  = threadIdx.x;
    int warp = tid >> 5;
    int lane = tid & 31;
    int g    = warp / 11;            // row band 0/1
    int w    = warp - 11*g;          // column warp
    int x    = 30*w + lane - 1;      // -1 .. 330
    bool inx = (x >= 0) && (x < WW);
    bool owner = (lane >= 1) && (lane <= 30) && (x < WW);
    int ybase = g*48 - 1;            // first (halo) row

    {   // fast hist zero (uint4)
        uint4* h4 = (uint4*)s_hist;
        for (int i = tid; i < NHIST/4; i += T1) h4[i] = make_uint4(0,0,0,0);
    }
    if (tid < NW) s_wcnt[tid] = 0;
    if (tid == 0){ s_ccnt = 0; s_thresh = 0; }

    const float NEG = -FLT_MAX;
    const float* colp = src + x;
    int* mycnt = &s_wcnt[warp];
    u64* mybuf = &s_surv[warp << 8];

    // prime 4-stage scalar pipeline with rows ybase..ybase+3
    float pf0 = (inx && ybase+0 >= 0) ? __ldg(colp + (ybase+0)*WW) : NEG;
    float pf1 =  inx                  ? __ldg(colp + (ybase+1)*WW) : NEG;
    float pf2 =  inx                  ? __ldg(colp + (ybase+2)*WW) : NEG;
    float pf3 =  inx                  ? __ldg(colp + (ybase+3)*WW) : NEG;

    float h1 = NEG, h0 = NEG, s_prev = NEG;

    __syncthreads();   // hist/wcnt ready before any emit

#define STEP(PFREG, YY_)                                                     \
    {                                                                        \
        const int yy = (YY_);                                                \
        float s = (yy < 50) ? (PFREG) : NEG;                                 \
        if (yy + 4 < 50){                                                    \
            int rn = ybase + yy + 4;                                         \
            PFREG = (inx && rn < HH) ? __ldg(colp + rn*WW) : NEG;            \
        }                                                                    \
        float lv = __shfl_up_sync(0xffffffffu, s, 1);                        \
        float rv = __shfl_down_sync(0xffffffffu, s, 1);                      \
        float h  = fmaxf(fmaxf(lv, rv), s);                                  \
        if (yy >= 2 && yy < 50 && owner){   /* emit rows ybase+1..ybase+48 */ \
            float vmax = fmaxf(fmaxf(h1, h0), h);                            \
            bool surv = (vmax == s_prev);                                    \
            if (!surv && (vmax - s_prev) < 1e-4f){                           \
                surv = (__float_as_uint(sigmoidf_(vmax)) ==                  \
                        __float_as_uint(sigmoidf_(s_prev)));                 \
            }                                                                \
            if (surv){                                                       \
                unsigned us = fsort(s_prev);                                 \
                atomicAdd(&s_hist[us >> 19], 1);                             \
                int pos = atomicAdd(mycnt, 1);                               \
                if (pos < WSURV)                                             \
                    mybuf[pos] = ((u64)us << 32) |                           \
                                 (unsigned)(~((ybase + yy - 1)*WW + x));     \
            }                                                                \
        }                                                                    \
        h1 = h0; h0 = h; s_prev = s;                                         \
    }

    for (int yb = 0; yb < 52; yb += 4){
        STEP(pf0, yb+0)
        STEP(pf1, yb+1)
        STEP(pf2, yb+2)
        STEP(pf3, yb+3)
    }
#undef STEP
    __syncthreads();

    // ---- radix-select: chunk partials + shfl scan (2 barriers) ----
    int psum = 0, incl = 0;
    if (tid < 256){
        int hi = NHIST - 32*tid;     // covers [hi-32, hi), chunks from top
        #pragma unroll
        for (int i = hi-32; i < hi; i++) psum += s_hist[i];
        incl = psum;
        #pragma unroll
        for (int off = 1; off < 32; off <<= 1){
            int v = __shfl_up_sync(0xffffffffu, incl, off);
            if (lane >= off) incl += v;
        }
        if (lane == 31) s_wsum[warp] = incl;   // warp 0..7
    }
    __syncthreads();
    if (tid < 256){
        int base2 = 0;
        #pragma unroll
        for (int q2 = 0; q2 < 8; q2++) base2 += (q2 < warp) ? s_wsum[q2] : 0;
        int inclg = incl + base2;
        int exclg = inclg - psum;
        if (exclg < KTOP && inclg >= KTOP){   // exactly one chunk crosses
            int hi2 = NHIST - 32*tid;
            int acc = exclg, thr = 0;
            for (int i = hi2-1; i >= hi2-32; i--){
                acc += s_hist[i];
                if (acc >= KTOP){ thr = i; break; }
            }
            s_thresh = (thr > 0) ? thr - 1 : 0;   // sigmoid-tie margin
        }
    }
    __syncthreads();

    // collect candidates, substituting sigmoid keys
    unsigned ut = (unsigned)s_thresh << 19;
    for (int i = tid; i < NW*WSURV; i += T1){
        int wi = i >> 8, o = i & (WSURV-1);
        if (o < s_wcnt[wi]){
            u64 key = s_surv[i];
            unsigned us = (unsigned)(key >> 32);
            if (us >= ut){
                int pos = atomicAdd(&s_ccnt, 1);
                if (pos < 512){
                    float sig = sigmoidf_(funsort(us));
                    s_key[pos] = ((u64)__float_as_uint(sig) << 32) | (unsigned)key;
                }
            }
        }
    }
    __syncthreads();

    // ---- RANK SORT: keys unique -> rank = #greater (1 barrier total) ----
    int nc = min(s_ccnt, 512);
    for (int i = tid; i < nc; i += T1){
        u64 me = s_key[i];
        int rank = 0;
        for (int q2 = 0; q2 < nc; q2++)
            rank += (s_key[q2] > me);
        if (rank < KTOP){
            g_scores[blk*KTOP + rank] = __uint_as_float((unsigned)(me >> 32));
            g_inds  [blk*KTOP + rank] = (int)(~(unsigned)me);
        }
    }

    // ================= global barrier (all 192 CTAs resident) ==========
    __threadfence();
    __syncthreads();
    if (tid == 0) atomicAdd(&g_done, 1u);
    if (blk >= NTAIL) return;                      // CTAs 160..191 done
    if (tid == 0){
        while (*((volatile unsigned*)&g_done) < (unsigned)(BATCH*NMAPS))
            __nanosleep(64);
        __threadfence();
    }
    __syncthreads();

    // ================= phase 2: tail ===================================
    int b2  = blk & 15;
    int job = blk >> 4;                            // 0..9

    u64*   ck  = (u64*)  smraw;                    // 300 keys   (2400 B)
    float* sfs = (float*)(smraw + 2400);           // 100
    int*   sfi = (int*)  (smraw + 2800);           // 100
    int*   sfc = (int*)  (smraw + 3200);           // 100
    float* hmx = (float*)(smraw + 3600);
    float* hmy = (float*)(smraw + 4000);
    float* hmsc= (float*)(smraw + 4400);
    float* bl  = (float*)(smraw + 4800);
    float* bt  = (float*)(smraw + 5200);
    float* br  = (float*)(smraw + 5600);
    float* bbm = (float*)(smraw + 6000);
    float* kx  = (float*)(smraw + 6400);
    float* ky  = (float*)(smraw + 6800);

    // ---- rank merge: 3 sorted channel lists -> global top-100 ----
    if (tid < 300){
        int c = tid / 100;
        float v = g_scores[(b2*NMAPS + c)*KTOP + (tid - c*100)];
        ck[tid] = ((u64)__float_as_uint(v) << 32) | (unsigned)(~(unsigned)tid);
    }
    __syncthreads();
    if (tid < 300){
        int c = tid / 100, r = tid - c*100;
        u64 me = ck[tid];
        int rank = r;
        #pragma unroll
        for (int c2 = 0; c2 < 3; c2++){
            if (c2 == c) continue;
            int lo = 0, hi2 = 100;
            while (lo < hi2){
                int mid = (lo + hi2) >> 1;
                if (ck[c2*100 + mid] > me) lo = mid + 1; else hi2 = mid;
            }
            rank += lo;
        }
        if (rank < KTOP){
            sfs[rank] = __uint_as_float((unsigned)(me >> 32));
            sfc[rank] = c;
            sfi[rank] = g_inds[(b2*NMAPS + c)*KTOP + r];
        }
    }
    __syncthreads();

    if (job == 9){
        // per-detection scalar fields
        if (tid < KTOP){
            int k = tid;
            int ind = sfi[k];
            float x0 = (float)(ind % WW);
            float y0 = (float)(ind / WW);
            float rx = reg[((size_t)b2*2 + 0)*HWSZ + ind];
            float ry = reg[((size_t)b2*2 + 1)*HWSZ + ind];
            float xs = x0 + rx, ys = y0 + ry;
            float w0 = wh[((size_t)b2*2 + 0)*HWSZ + ind];
            float w1 = wh[((size_t)b2*2 + 1)*HWSZ + ind];
            float* det = out + ((size_t)b2*KTOP + k)*45;
            det[0] = (xs - w0*0.5f)*4.0f;
            det[1] = (ys - w1*0.5f)*4.0f;
            det[2] = (xs + w0*0.5f)*4.0f;
            det[3] = (ys + w1*0.5f)*4.0f;
            det[4] = sfs[k];
            det[23] = dim[((size_t)b2*3 + 0)*HWSZ + ind];
            det[24] = dim[((size_t)b2*3 + 1)*HWSZ + ind];
            det[25] = dim[((size_t)b2*3 + 2)*HWSZ + ind];
            #pragma unroll
            for (int c = 0; c < 8; c++)
                det[35 + c] = rot[((size_t)b2*8 + c)*HWSZ + ind];
            det[43] = prob[(size_t)b2*HWSZ + ind];
            det[44] = (float)sfc[k];
        }
    } else {
        int j = job;
        if (tid < KTOP){
            int k = tid;
            int base = (b2*NMAPS + 3 + j)*KTOP + k;
            int ind  = g_inds[base];
            float sc = g_scores[base];
            int ind2 = sfi[k];
            float ox = hp_offset[((size_t)b2*2 + 0)*HWSZ + ind];
            float oy = hp_offset[((size_t)b2*2 + 1)*HWSZ + ind];
            float rx = reg[((size_t)b2*2 + 0)*HWSZ + ind2];
            float ry = reg[((size_t)b2*2 + 1)*HWSZ + ind2];
            float w0 = wh[((size_t)b2*2 + 0)*HWSZ + ind2];
            float w1 = wh[((size_t)b2*2 + 1)*HWSZ + ind2];
            float hx0 = hps[((size_t)b2*18 + 2*j    )*HWSZ + ind2];
            float hy0 = hps[((size_t)b2*18 + 2*j + 1)*HWSZ + ind2];

            float xq = (float)(ind % WW) + ox;
            float yq = (float)(ind / WW) + oy;
            bool valid = sc > THRESH;
            hmsc[k] = valid ? sc : -1.0f;
            hmx [k] = valid ? xq : -10000.0f;
            hmy [k] = valid ? yq : -10000.0f;

            float x0 = (float)(ind2 % WW);
            float y0 = (float)(ind2 / WW);
            float xs = x0 + rx, ys = y0 + ry;
            bl[k] = xs - w0*0.5f; bt[k]  = ys - w1*0.5f;
            br[k] = xs + w0*0.5f; bbm[k] = ys + w1*0.5f;
            kx[k] = hx0 + x0;
            ky[k] = hy0 + y0;
        }
        __syncthreads();

        if (tid < KTOP){
            int k = tid;
            float px = kx[k], py = ky[k];
            float bsq = FLT_MAX; int bm = 0;
            #pragma unroll 4
            for (int mm = 0; mm < 100; mm++){
                float dx = px - hmx[mm];
                float dy = py - hmy[mm];
                float sq = dx*dx + dy*dy;
                if (sq < bsq){ bsq = sq; bm = mm; }
            }
            float smin = sqrtf(bsq);
            float lim = bsq * 1.000001f;   // sqrt rounding collapse window
            for (int mm = 0; mm < bm; mm++){
                float dx = px - hmx[mm];
                float dy = py - hmy[mm];
                float sq = dx*dx + dy*dy;
                if (sq <= lim && sqrtf(sq) == smin){ bm = mm; break; }
            }
            float hs = hmsc[bm], hx = hmx[bm], hy = hmy[bm];
            float l = bl[k], tt = bt[k], r = br[k], bo = bbm[k];
            bool invalid = (hx < l) || (hx > r) || (hy < tt) || (hy > bo) ||
                           (hs < THRESH) ||
                           (smin > fmaxf(bo - tt, r - l)*0.3f);
            float fx = invalid ? px : hx;
            float fy = invalid ? py : hy;
            float* det = out + ((size_t)b2*KTOP + k)*45;
            det[5 + 2*j] = fx*4.0f;
            det[6 + 2*j] = fy*4.0f;
            det[26 + j]  = hs;
        }
    }

    // ---- counter reset for graph replays (last tail CTA cleans up) ----
    __syncthreads();
    if (tid == 0){
        unsigned d = atomicAdd(&g_done2, 1u);
        if (d == (unsigned)(NTAIL - 1)){
            g_done = 0u;
            __threadfence();
            atomicExch(&g_done2, 0u);
        }
    }
}

// =====================================================================
extern "C" void kernel_launch(void* const* d_in, const int* in_sizes, int n_in,
                              void* d_out, int out_size){
    const float* hm        = (const float*)d_in[0];
    const float* wh        = (const float*)d_in[1];
    const float* hps       = (const float*)d_in[2];
    const float* dim       = (const float*)d_in[3];
    const float* rot       = (const float*)d_in[4];
    const float* prob      = (const float*)d_in[5];
    const float* reg       = (const float*)d_in[6];
    const float* hm_hp     = (const float*)d_in[7];
    const float* hp_offset = (const float*)d_in[8];
    float* out = (float*)d_out;

    const int SMEM1 = 45056 + 32768 + 4096 + 128;   // 82048 B
    cudaFuncSetAttribute(km3d_kernel,
                         cudaFuncAttributeMaxDynamicSharedMemorySize, SMEM1);

    km3d_kernel<<<BATCH*NMAPS, T1, SMEM1>>>(hm, hm_hp, wh, hps, dim, rot,
                                            prob, reg, hp_offset, out);
}

// round 16
// speedup vs baseline: 1.5161x; 1.0146x over previous
#include <cuda_runtime.h>
#include <cstdint>
#include <float.h>

#define BATCH 16
#define HH 96
#define WW 320
#define HWSZ (HH*WW)      // 30720
#define KTOP 100
#define NMAPS 12          // 3 hm + 9 hm_hp
#define THRESH 0.1f

#define T1 704            // 22 warps: 2 row-bands x 11 column-warps
#define NW 22
#define WSURV 256         // survivor slots per warp (power of 2)
#define NHIST 8192
#define NTAIL 160         // 10 jobs x 16 batches

typedef unsigned long long u64;

// ---------------- scratch (no cudaMalloc allowed) ----------------
__device__ float    g_scores[BATCH*NMAPS*KTOP];
__device__ int      g_inds  [BATCH*NMAPS*KTOP];
__device__ unsigned g_done  = 0;   // phase-1 completion counter
__device__ unsigned g_done2 = 0;   // tail completion counter (for reset)

__device__ __forceinline__ float sigmoidf_(float x){ return 1.0f/(1.0f + expf(-x)); }

// sortable uint from float bits (monotone, handles negatives)
__device__ __forceinline__ unsigned fsort(float f){
    unsigned u = __float_as_uint(f);
    return u ^ (((unsigned)((int)u >> 31)) | 0x80000000u);
}
__device__ __forceinline__ float funsort(unsigned us){
    unsigned u = (us & 0x80000000u) ? (us ^ 0x80000000u) : ~us;
    return __uint_as_float(u);
}

// =====================================================================
// ONE persistent kernel.
// Phase 1 (192 CTAs): streaming RAW 3x3 NMS + top-100 per map.
//   CLAMPED addressing: boundary duplication is a no-op for max-stencils,
//   so ALL loads are unconditional (no inx/NEG/bounds logic in hot loop).
// Global barrier (all 192 CTAs resident in one wave).
// Phase 2 (CTAs 0..159): rank-merge 300->100 + gathers / joint matching.
// =====================================================================
__global__ __launch_bounds__(T1, 2)
void km3d_kernel(const float* __restrict__ hm,  const float* __restrict__ hm_hp,
                 const float* __restrict__ wh,  const float* __restrict__ hps,
                 const float* __restrict__ dim, const float* __restrict__ rot,
                 const float* __restrict__ prob,const float* __restrict__ reg,
                 const float* __restrict__ hp_offset, float* __restrict__ out){
    int blk = blockIdx.x;            // phase 1: b*NMAPS + map
    int b   = blk / NMAPS;
    int map = blk - b*NMAPS;
    const float* src = (map < 3) ? (hm    + (size_t)(b*3 +  map     )*HWSZ)
                                 : (hm_hp + (size_t)(b*9 + (map - 3))*HWSZ);

    extern __shared__ char smraw[];
    u64* s_surv = (u64*)smraw;                        // NW*WSURV*8 = 45056
    int* s_hist = (int*)(smraw + 45056);              // 8192*4 = 32768
    u64* s_key  = (u64*)(smraw + 77824);              // 512*8  = 4096
    int* s_wcnt = (int*)(smraw + 81920);              // 22*4
    __shared__ int s_ccnt, s_thresh;
    __shared__ int s_wsum[8];

    int tid  = threadIdx.x;
    int warp = tid >> 5;
    int lane = tid & 31;
    int g    = warp / 11;            // row band 0/1
    int w    = warp - 11*g;          // column warp
    int x    = 30*w + lane - 1;      // -1 .. 330
    int x_cl = min(max(x, 0), WW-1); // clamped column (self-dup at edges)
    bool owner = (lane >= 1) && (lane <= 30) && (x < WW);
    int ybase = g*48 - 1;            // first (halo) row

    {   // fast hist zero (uint4)
        uint4* h4 = (uint4*)s_hist;
        for (int i = tid; i < NHIST/4; i += T1) h4[i] = make_uint4(0,0,0,0);
    }
    if (tid < NW) s_wcnt[tid] = 0;
    if (tid == 0){ s_ccnt = 0; s_thresh = 0; }

    const float NEG = -FLT_MAX;
    const float* colp = src + x_cl;
    int* mycnt = &s_wcnt[warp];
    u64* mybuf = &s_surv[warp << 8];

    // prime 4-stage scalar pipeline with clamped rows ybase..ybase+3
    float pf0 = __ldg(colp + min(max(ybase+0, 0), HH-1)*WW);
    float pf1 = __ldg(colp + min(max(ybase+1, 0), HH-1)*WW);
    float pf2 = __ldg(colp + min(max(ybase+2, 0), HH-1)*WW);
    float pf3 = __ldg(colp + min(max(ybase+3, 0), HH-1)*WW);

    float h1 = NEG, h0 = NEG, s_prev = NEG;

    __syncthreads();   // hist/wcnt ready before any emit

#define STEP(PFREG, YY_)                                                     \
    {                                                                        \
        const int yy = (YY_);                                                \
        float s = PFREG;                                                     \
        if (yy + 4 < 50)                                                     \
            PFREG = __ldg(colp + min(ybase + yy + 4, HH-1)*WW);              \
        float lv = __shfl_up_sync(0xffffffffu, s, 1);                        \
        float rv = __shfl_down_sync(0xffffffffu, s, 1);                      \
        float h  = fmaxf(fmaxf(lv, rv), s);                                  \
        if (yy >= 2 && owner){              /* emit row ybase+yy-1 */        \
            float vmax = fmaxf(fmaxf(h1, h0), h);                            \
            bool surv = (vmax == s_prev);                                    \
            if (!surv && (vmax - s_prev) < 1e-4f){                           \
                surv = (__float_as_uint(sigmoidf_(vmax)) ==                  \
                        __float_as_uint(sigmoidf_(s_prev)));                 \
            }                                                                \
            if (surv){                                                       \
                unsigned us = fsort(s_prev);                                 \
                atomicAdd(&s_hist[us >> 19], 1);                             \
                int pos = atomicAdd(mycnt, 1);                               \
                if (pos < WSURV)                                             \
                    mybuf[pos] = ((u64)us << 32) |                           \
                                 (unsigned)(~((ybase + yy - 1)*WW + x));     \
            }                                                                \
        }                                                                    \
        h1 = h0; h0 = h; s_prev = s;                                         \
    }

    // exactly 50 streamed rows (yy = 0..49); emission at yy = 2..49
    for (int yb = 0; yb < 48; yb += 4){
        STEP(pf0, yb+0)
        STEP(pf1, yb+1)
        STEP(pf2, yb+2)
        STEP(pf3, yb+3)
    }
    STEP(pf0, 48)
    STEP(pf1, 49)
#undef STEP
    __syncthreads();

    // ---- radix-select: chunk partials + shfl scan (2 barriers) ----
    int psum = 0, incl = 0;
    if (tid < 256){
        int hi = NHIST - 32*tid;     // covers [hi-32, hi), chunks from top
        #pragma unroll
        for (int i = hi-32; i < hi; i++) psum += s_hist[i];
        incl = psum;
        #pragma unroll
        for (int off = 1; off < 32; off <<= 1){
            int v = __shfl_up_sync(0xffffffffu, incl, off);
            if (lane >= off) incl += v;
        }
        if (lane == 31) s_wsum[warp] = incl;   // warp 0..7
    }
    __syncthreads();
    if (tid < 256){
        int base2 = 0;
        #pragma unroll
        for (int q2 = 0; q2 < 8; q2++) base2 += (q2 < warp) ? s_wsum[q2] : 0;
        int inclg = incl + base2;
        int exclg = inclg - psum;
        if (exclg < KTOP && inclg >= KTOP){   // exactly one chunk crosses
            int hi2 = NHIST - 32*tid;
            int acc = exclg, thr = 0;
            for (int i = hi2-1; i >= hi2-32; i--){
                acc += s_hist[i];
                if (acc >= KTOP){ thr = i; break; }
            }
            s_thresh = (thr > 0) ? thr - 1 : 0;   // sigmoid-tie margin
        }
    }
    __syncthreads();

    // collect candidates, substituting sigmoid keys
    unsigned ut = (unsigned)s_thresh << 19;
    for (int i = tid; i < NW*WSURV; i += T1){
        int wi = i >> 8, o = i & (WSURV-1);
        if (o < s_wcnt[wi]){
            u64 key = s_surv[i];
            unsigned us = (unsigned)(key >> 32);
            if (us >= ut){
                int pos = atomicAdd(&s_ccnt, 1);
                if (pos < 512){
                    float sig = sigmoidf_(funsort(us));
                    s_key[pos] = ((u64)__float_as_uint(sig) << 32) | (unsigned)key;
                }
            }
        }
    }
    __syncthreads();

    // ---- RANK SORT: keys unique -> rank = #greater ----
    int nc = min(s_ccnt, 512);
    for (int i = tid; i < nc; i += T1){
        u64 me = s_key[i];
        int rank = 0;
        for (int q2 = 0; q2 < nc; q2++)
            rank += (s_key[q2] > me);
        if (rank < KTOP){
            g_scores[blk*KTOP + rank] = __uint_as_float((unsigned)(me >> 32));
            g_inds  [blk*KTOP + rank] = (int)(~(unsigned)me);
        }
    }

    // ================= global barrier (all 192 CTAs resident) ==========
    __threadfence();
    __syncthreads();
    if (tid == 0) atomicAdd(&g_done, 1u);
    if (blk >= NTAIL) return;                      // CTAs 160..191 done
    if (tid == 0){
        while (*((volatile unsigned*)&g_done) < (unsigned)(BATCH*NMAPS))
            __nanosleep(64);
        __threadfence();
    }
    __syncthreads();

    // ================= phase 2: tail ===================================
    int b2  = blk & 15;
    int job = blk >> 4;                            // 0..9

    u64*   ck  = (u64*)  smraw;                    // 300 keys   (2400 B)
    float* sfs = (float*)(smraw + 2400);           // 100
    int*   sfi = (int*)  (smraw + 2800);           // 100
    int*   sfc = (int*)  (smraw + 3200);           // 100
    float* hmx = (float*)(smraw + 3600);
    float* hmy = (float*)(smraw + 4000);
    float* hmsc= (float*)(smraw + 4400);
    float* bl  = (float*)(smraw + 4800);
    float* bt  = (float*)(smraw + 5200);
    float* br  = (float*)(smraw + 5600);
    float* bbm = (float*)(smraw + 6000);
    float* kx  = (float*)(smraw + 6400);
    float* ky  = (float*)(smraw + 6800);

    // ---- rank merge: 3 sorted channel lists -> global top-100 ----
    if (tid < 300){
        int c = tid / 100;
        float v = g_scores[(b2*NMAPS + c)*KTOP + (tid - c*100)];
        ck[tid] = ((u64)__float_as_uint(v) << 32) | (unsigned)(~(unsigned)tid);
    }
    __syncthreads();
    if (tid < 300){
        int c = tid / 100, r = tid - c*100;
        u64 me = ck[tid];
        int rank = r;
        #pragma unroll
        for (int c2 = 0; c2 < 3; c2++){
            if (c2 == c) continue;
            int lo = 0, hi2 = 100;
            while (lo < hi2){
                int mid = (lo + hi2) >> 1;
                if (ck[c2*100 + mid] > me) lo = mid + 1; else hi2 = mid;
            }
            rank += lo;
        }
        if (rank < KTOP){
            sfs[rank] = __uint_as_float((unsigned)(me >> 32));
            sfc[rank] = c;
            sfi[rank] = g_inds[(b2*NMAPS + c)*KTOP + r];
        }
    }
    __syncthreads();

    if (job == 9){
        // per-detection scalar fields
        if (tid < KTOP){
            int k = tid;
            int ind = sfi[k];
            float x0 = (float)(ind % WW);
            float y0 = (float)(ind / WW);
            float rx = reg[((size_t)b2*2 + 0)*HWSZ + ind];
            float ry = reg[((size_t)b2*2 + 1)*HWSZ + ind];
            float xs = x0 + rx, ys = y0 + ry;
            float w0 = wh[((size_t)b2*2 + 0)*HWSZ + ind];
            float w1 = wh[((size_t)b2*2 + 1)*HWSZ + ind];
            float* det = out + ((size_t)b2*KTOP + k)*45;
            det[0] = (xs - w0*0.5f)*4.0f;
            det[1] = (ys - w1*0.5f)*4.0f;
            det[2] = (xs + w0*0.5f)*4.0f;
            det[3] = (ys + w1*0.5f)*4.0f;
            det[4] = sfs[k];
            det[23] = dim[((size_t)b2*3 + 0)*HWSZ + ind];
            det[24] = dim[((size_t)b2*3 + 1)*HWSZ + ind];
            det[25] = dim[((size_t)b2*3 + 2)*HWSZ + ind];
            #pragma unroll
            for (int c = 0; c < 8; c++)
                det[35 + c] = rot[((size_t)b2*8 + c)*HWSZ + ind];
            det[43] = prob[(size_t)b2*HWSZ + ind];
            det[44] = (float)sfc[k];
        }
    } else {
        int j = job;
        if (tid < KTOP){
            int k = tid;
            int base = (b2*NMAPS + 3 + j)*KTOP + k;
            int ind  = g_inds[base];
            float sc = g_scores[base];
            int ind2 = sfi[k];
            float ox = hp_offset[((size_t)b2*2 + 0)*HWSZ + ind];
            float oy = hp_offset[((size_t)b2*2 + 1)*HWSZ + ind];
            float rx = reg[((size_t)b2*2 + 0)*HWSZ + ind2];
            float ry = reg[((size_t)b2*2 + 1)*HWSZ + ind2];
            float w0 = wh[((size_t)b2*2 + 0)*HWSZ + ind2];
            float w1 = wh[((size_t)b2*2 + 1)*HWSZ + ind2];
            float hx0 = hps[((size_t)b2*18 + 2*j    )*HWSZ + ind2];
            float hy0 = hps[((size_t)b2*18 + 2*j + 1)*HWSZ + ind2];

            float xq = (float)(ind % WW) + ox;
            float yq = (float)(ind / WW) + oy;
            bool valid = sc > THRESH;
            hmsc[k] = valid ? sc : -1.0f;
            hmx [k] = valid ? xq : -10000.0f;
            hmy [k] = valid ? yq : -10000.0f;

            float x0 = (float)(ind2 % WW);
            float y0 = (float)(ind2 / WW);
            float xs = x0 + rx, ys = y0 + ry;
            bl[k] = xs - w0*0.5f; bt[k]  = ys - w1*0.5f;
            br[k] = xs + w0*0.5f; bbm[k] = ys + w1*0.5f;
            kx[k] = hx0 + x0;
            ky[k] = hy0 + y0;
        }
        __syncthreads();

        if (tid < KTOP){
            int k = tid;
            float px = kx[k], py = ky[k];
            float bsq = FLT_MAX; int bm = 0;
            #pragma unroll 4
            for (int mm = 0; mm < 100; mm++){
                float dx = px - hmx[mm];
                float dy = py - hmy[mm];
                float sq = dx*dx + dy*dy;
                if (sq < bsq){ bsq = sq; bm = mm; }
            }
            float smin = sqrtf(bsq);
            float lim = bsq * 1.000001f;   // sqrt rounding collapse window
            for (int mm = 0; mm < bm; mm++){
                float dx = px - hmx[mm];
                float dy = py - hmy[mm];
                float sq = dx*dx + dy*dy;
                if (sq <= lim && sqrtf(sq) == smin){ bm = mm; break; }
            }
            float hs = hmsc[bm], hx = hmx[bm], hy = hmy[bm];
            float l = bl[k], tt = bt[k], r = br[k], bo = bbm[k];
            bool invalid = (hx < l) || (hx > r) || (hy < tt) || (hy > bo) ||
                           (hs < THRESH) ||
                           (smin > fmaxf(bo - tt, r - l)*0.3f);
            float fx = invalid ? px : hx;
            float fy = invalid ? py : hy;
            float* det = out + ((size_t)b2*KTOP + k)*45;
            det[5 + 2*j] = fx*4.0f;
            det[6 + 2*j] = fy*4.0f;
            det[26 + j]  = hs;
        }
    }

    // ---- counter reset for graph replays (last tail CTA cleans up) ----
    __syncthreads();
    if (tid == 0){
        unsigned d = atomicAdd(&g_done2, 1u);
        if (d == (unsigned)(NTAIL - 1)){
            g_done = 0u;
            __threadfence();
            atomicExch(&g_done2, 0u);
        }
    }
}

// =====================================================================
extern "C" void kernel_launch(void* const* d_in, const int* in_sizes, int n_in,
                              void* d_out, int out_size){
    const float* hm        = (const float*)d_in[0];
    const float* wh        = (const float*)d_in[1];
    const float* hps       = (const float*)d_in[2];
    const float* dim       = (const float*)d_in[3];
    const float* rot       = (const float*)d_in[4];
    const float* prob      = (const float*)d_in[5];
    const float* reg       = (const float*)d_in[6];
    const float* hm_hp     = (const float*)d_in[7];
    const float* hp_offset = (const float*)d_in[8];
    float* out = (float*)d_out;

    const int SMEM1 = 45056 + 32768 + 4096 + 128;   // 82048 B
    cudaFuncSetAttribute(km3d_kernel,
                         cudaFuncAttributeMaxDynamicSharedMemorySize, SMEM1);

    km3d_kernel<<<BATCH*NMAPS, T1, SMEM1>>>(hm, hm_hp, wh, hps, dim, rot,
                                            prob, reg, hp_offset, out);
}

// round 17
// speedup vs baseline: 1.5364x; 1.0134x over previous
#include <cuda_runtime.h>
#include <cstdint>
#include <float.h>

#define BATCH 16
#define HH 96
#define WW 320
#define HWSZ (HH*WW)      // 30720
#define KTOP 100
#define NMAPS 12          // 3 hm + 9 hm_hp
#define THRESH 0.1f

#define T1 704            // 22 warps: 2 row-bands x 11 column-warps
#define NW 22
#define WSURV 256         // survivor slots per warp (power of 2)
#define NHIST 8192
#define NTAIL 160         // 10 jobs x 16 batches

typedef unsigned long long u64;

// ---------------- scratch (no cudaMalloc allowed) ----------------
__device__ float    g_scores[BATCH*NMAPS*KTOP];
__device__ int      g_inds  [BATCH*NMAPS*KTOP];
__device__ unsigned g_done  = 0;   // phase-1 completion counter
__device__ unsigned g_done2 = 0;   // tail completion counter (for reset)

__device__ __forceinline__ float sigmoidf_(float x){ return 1.0f/(1.0f + expf(-x)); }

// sortable uint from float bits (monotone, handles negatives)
__device__ __forceinline__ unsigned fsort(float f){
    unsigned u = __float_as_uint(f);
    return u ^ (((unsigned)((int)u >> 31)) | 0x80000000u);
}
__device__ __forceinline__ float funsort(unsigned us){
    unsigned u = (us & 0x80000000u) ? (us ^ 0x80000000u) : ~us;
    return __uint_as_float(u);
}

// =====================================================================
// ONE persistent kernel.
// Phase 1 (192 CTAs): streaming RAW 3x3 NMS + top-100 per map.
//   Clamped addressing (boundary dup is a no-op for max-stencils);
//   6-deep scalar prefetch; per-warp survivor buffers + per-warp collect;
//   shfl radix-select; rank sort.
// Global barrier (all 192 CTAs resident in one wave).
// Phase 2 (CTAs 0..159): rank-merge 300->100 + gathers / joint matching.
// =====================================================================
__global__ __launch_bounds__(T1, 2)
void km3d_kernel(const float* __restrict__ hm,  const float* __restrict__ hm_hp,
                 const float* __restrict__ wh,  const float* __restrict__ hps,
                 const float* __restrict__ dim, const float* __restrict__ rot,
                 const float* __restrict__ prob,const float* __restrict__ reg,
                 const float* __restrict__ hp_offset, float* __restrict__ out){
    int blk = blockIdx.x;            // phase 1: b*NMAPS + map
    int b   = blk / NMAPS;
    int map = blk - b*NMAPS;
    const float* src = (map < 3) ? (hm    + (size_t)(b*3 +  map     )*HWSZ)
                                 : (hm_hp + (size_t)(b*9 + (map - 3))*HWSZ);

    extern __shared__ char smraw[];
    u64* s_surv = (u64*)smraw;                        // NW*WSURV*8 = 45056
    int* s_hist = (int*)(smraw + 45056);              // 8192*4 = 32768
    u64* s_key  = (u64*)(smraw + 77824);              // 512*8  = 4096
    int* s_wcnt = (int*)(smraw + 81920);              // 22*4
    __shared__ int s_ccnt, s_thresh;
    __shared__ int s_wsum[8];

    int tid  = threadIdx.x;
    int warp = tid >> 5;
    int lane = tid & 31;
    int g    = warp / 11;            // row band 0/1
    int w    = warp - 11*g;          // column warp
    int x    = 30*w + lane - 1;      // -1 .. 330
    int x_cl = min(max(x, 0), WW-1); // clamped column (self-dup at edges)
    bool owner = (lane >= 1) && (lane <= 30) && (x < WW);
    int ybase = g*48 - 1;            // first (halo) row

    {   // fast hist zero (uint4)
        uint4* h4 = (uint4*)s_hist;
        for (int i = tid; i < NHIST/4; i += T1) h4[i] = make_uint4(0,0,0,0);
    }
    if (tid < NW) s_wcnt[tid] = 0;
    if (tid == 0){ s_ccnt = 0; s_thresh = 0; }

    const float NEG = -FLT_MAX;
    const float* colp = src + x_cl;
    int* mycnt = &s_wcnt[warp];
    u64* mybuf = &s_surv[warp << 8];

    // prime 6-stage scalar pipeline with clamped rows ybase..ybase+5
    float pf0 = __ldg(colp + min(max(ybase+0, 0), HH-1)*WW);
    float pf1 = __ldg(colp + min(max(ybase+1, 0), HH-1)*WW);
    float pf2 = __ldg(colp + min(max(ybase+2, 0), HH-1)*WW);
    float pf3 = __ldg(colp + min(max(ybase+3, 0), HH-1)*WW);
    float pf4 = __ldg(colp + min(max(ybase+4, 0), HH-1)*WW);
    float pf5 = __ldg(colp + min(max(ybase+5, 0), HH-1)*WW);

    float h1 = NEG, h0 = NEG, s_prev = NEG;

    __syncthreads();   // hist/wcnt ready before any emit

#define STEP(PFREG, YY_)                                                     \
    {                                                                        \
        const int yy = (YY_);                                                \
        float s = PFREG;                                                     \
        if (yy + 6 < 50)                                                     \
            PFREG = __ldg(colp + min(ybase + yy + 6, HH-1)*WW);              \
        float lv = __shfl_up_sync(0xffffffffu, s, 1);                        \
        float rv = __shfl_down_sync(0xffffffffu, s, 1);                      \
        float h  = fmaxf(fmaxf(lv, rv), s);                                  \
        if (yy >= 2 && owner){              /* emit row ybase+yy-1 */        \
            float vmax = fmaxf(fmaxf(h1, h0), h);                            \
            bool surv = (vmax == s_prev);                                    \
            if (!surv && (vmax - s_prev) < 1e-4f){                           \
                surv = (__float_as_uint(sigmoidf_(vmax)) ==                  \
                        __float_as_uint(sigmoidf_(s_prev)));                 \
            }                                                                \
            if (surv){                                                       \
                unsigned us = fsort(s_prev);                                 \
                atomicAdd(&s_hist[us >> 19], 1);                             \
                int pos = atomicAdd(mycnt, 1);                               \
                if (pos < WSURV)                                             \
                    mybuf[pos] = ((u64)us << 32) |                           \
                                 (unsigned)(~((ybase + yy - 1)*WW + x));     \
            }                                                                \
        }                                                                    \
        h1 = h0; h0 = h; s_prev = s;                                         \
    }

    // exactly 50 streamed rows (yy = 0..49); emission at yy = 2..49
    for (int yb = 0; yb < 48; yb += 6){
        STEP(pf0, yb+0)
        STEP(pf1, yb+1)
        STEP(pf2, yb+2)
        STEP(pf3, yb+3)
        STEP(pf4, yb+4)
        STEP(pf5, yb+5)
    }
    STEP(pf0, 48)
    STEP(pf1, 49)
#undef STEP
    __syncthreads();

    // ---- radix-select: chunk partials + shfl scan (2 barriers) ----
    int psum = 0, incl = 0;
    if (tid < 256){
        int hi = NHIST - 32*tid;     // covers [hi-32, hi), chunks from top
        #pragma unroll
        for (int i = hi-32; i < hi; i++) psum += s_hist[i];
        incl = psum;
        #pragma unroll
        for (int off = 1; off < 32; off <<= 1){
            int v = __shfl_up_sync(0xffffffffu, incl, off);
            if (lane >= off) incl += v;
        }
        if (lane == 31) s_wsum[warp] = incl;   // warp 0..7
    }
    __syncthreads();
    if (tid < 256){
        int base2 = 0;
        #pragma unroll
        for (int q2 = 0; q2 < 8; q2++) base2 += (q2 < warp) ? s_wsum[q2] : 0;
        int inclg = incl + base2;
        int exclg = inclg - psum;
        if (exclg < KTOP && inclg >= KTOP){   // exactly one chunk crosses
            int hi2 = NHIST - 32*tid;
            int acc = exclg, thr = 0;
            for (int i = hi2-1; i >= hi2-32; i--){
                acc += s_hist[i];
                if (acc >= KTOP){ thr = i; break; }
            }
            s_thresh = (thr > 0) ? thr - 1 : 0;   // sigmoid-tie margin
        }
    }
    __syncthreads();

    // collect candidates (per-warp: each warp scans its own buffer)
    unsigned ut = (unsigned)s_thresh << 19;
    {
        int wn = min(*mycnt, WSURV);
        for (int o = lane; o < wn; o += 32){
            u64 key = mybuf[o];
            unsigned us = (unsigned)(key >> 32);
            if (us >= ut){
                int pos = atomicAdd(&s_ccnt, 1);
                if (pos < 512){
                    float sig = sigmoidf_(funsort(us));
                    s_key[pos] = ((u64)__float_as_uint(sig) << 32) | (unsigned)key;
                }
            }
        }
    }
    __syncthreads();

    // ---- RANK SORT: keys unique -> rank = #greater ----
    int nc = min(s_ccnt, 512);
    for (int i = tid; i < nc; i += T1){
        u64 me = s_key[i];
        int rank = 0;
        for (int q2 = 0; q2 < nc; q2++)
            rank += (s_key[q2] > me);
        if (rank < KTOP){
            g_scores[blk*KTOP + rank] = __uint_as_float((unsigned)(me >> 32));
            g_inds  [blk*KTOP + rank] = (int)(~(unsigned)me);
        }
    }

    // ================= global barrier (all 192 CTAs resident) ==========
    __threadfence();
    __syncthreads();
    if (tid == 0) atomicAdd(&g_done, 1u);
    if (blk >= NTAIL) return;                      // CTAs 160..191 done
    if (tid == 0){
        while (*((volatile unsigned*)&g_done) < (unsigned)(BATCH*NMAPS))
            __nanosleep(64);
        __threadfence();
    }
    __syncthreads();

    // ================= phase 2: tail ===================================
    int b2  = blk & 15;
    int job = blk >> 4;                            // 0..9

    u64*   ck  = (u64*)  smraw;                    // 300 keys   (2400 B)
    float* sfs = (float*)(smraw + 2400);           // 100
    int*   sfi = (int*)  (smraw + 2800);           // 100
    int*   sfc = (int*)  (smraw + 3200);           // 100
    float* hmx = (float*)(smraw + 3600);
    float* hmy = (float*)(smraw + 4000);
    float* hmsc= (float*)(smraw + 4400);
    float* bl  = (float*)(smraw + 4800);
    float* bt  = (float*)(smraw + 5200);
    float* br  = (float*)(smraw + 5600);
    float* bbm = (float*)(smraw + 6000);
    float* kx  = (float*)(smraw + 6400);
    float* ky  = (float*)(smraw + 6800);

    // ---- rank merge: 3 sorted channel lists -> global top-100 ----
    if (tid < 300){
        int c = tid / 100;
        float v = g_scores[(b2*NMAPS + c)*KTOP + (tid - c*100)];
        ck[tid] = ((u64)__float_as_uint(v) << 32) | (unsigned)(~(unsigned)tid);
    }
    __syncthreads();
    if (tid < 300){
        int c = tid / 100, r = tid - c*100;
        u64 me = ck[tid];
        int rank = r;
        #pragma unroll
        for (int c2 = 0; c2 < 3; c2++){
            if (c2 == c) continue;
            int lo = 0, hi2 = 100;
            while (lo < hi2){
                int mid = (lo + hi2) >> 1;
                if (ck[c2*100 + mid] > me) lo = mid + 1; else hi2 = mid;
            }
            rank += lo;
        }
        if (rank < KTOP){
            sfs[rank] = __uint_as_float((unsigned)(me >> 32));
            sfc[rank] = c;
            sfi[rank] = g_inds[(b2*NMAPS + c)*KTOP + r];
        }
    }
    __syncthreads();

    if (job == 9){
        // per-detection scalar fields
        if (tid < KTOP){
            int k = tid;
            int ind = sfi[k];
            float x0 = (float)(ind % WW);
            float y0 = (float)(ind / WW);
            float rx = reg[((size_t)b2*2 + 0)*HWSZ + ind];
            float ry = reg[((size_t)b2*2 + 1)*HWSZ + ind];
            float xs = x0 + rx, ys = y0 + ry;
            float w0 = wh[((size_t)b2*2 + 0)*HWSZ + ind];
            float w1 = wh[((size_t)b2*2 + 1)*HWSZ + ind];
            float* det = out + ((size_t)b2*KTOP + k)*45;
            det[0] = (xs - w0*0.5f)*4.0f;
            det[1] = (ys - w1*0.5f)*4.0f;
            det[2] = (xs + w0*0.5f)*4.0f;
            det[3] = (ys + w1*0.5f)*4.0f;
            det[4] = sfs[k];
            det[23] = dim[((size_t)b2*3 + 0)*HWSZ + ind];
            det[24] = dim[((size_t)b2*3 + 1)*HWSZ + ind];
            det[25] = dim[((size_t)b2*3 + 2)*HWSZ + ind];
            #pragma unroll
            for (int c = 0; c < 8; c++)
                det[35 + c] = rot[((size_t)b2*8 + c)*HWSZ + ind];
            det[43] = prob[(size_t)b2*HWSZ + ind];
            det[44] = (float)sfc[k];
        }
    } else {
        int j = job;
        if (tid < KTOP){
            int k = tid;
            int base = (b2*NMAPS + 3 + j)*KTOP + k;
            int ind  = g_inds[base];
            float sc = g_scores[base];
            int ind2 = sfi[k];
            float ox = hp_offset[((size_t)b2*2 + 0)*HWSZ + ind];
            float oy = hp_offset[((size_t)b2*2 + 1)*HWSZ + ind];
            float rx = reg[((size_t)b2*2 + 0)*HWSZ + ind2];
            float ry = reg[((size_t)b2*2 + 1)*HWSZ + ind2];
            float w0 = wh[((size_t)b2*2 + 0)*HWSZ + ind2];
            float w1 = wh[((size_t)b2*2 + 1)*HWSZ + ind2];
            float hx0 = hps[((size_t)b2*18 + 2*j    )*HWSZ + ind2];
            float hy0 = hps[((size_t)b2*18 + 2*j + 1)*HWSZ + ind2];

            float xq = (float)(ind % WW) + ox;
            float yq = (float)(ind / WW) + oy;
            bool valid = sc > THRESH;
            hmsc[k] = valid ? sc : -1.0f;
            hmx [k] = valid ? xq : -10000.0f;
            hmy [k] = valid ? yq : -10000.0f;

            float x0 = (float)(ind2 % WW);
            float y0 = (float)(ind2 / WW);
            float xs = x0 + rx, ys = y0 + ry;
            bl[k] = xs - w0*0.5f; bt[k]  = ys - w1*0.5f;
            br[k] = xs + w0*0.5f; bbm[k] = ys + w1*0.5f;
            kx[k] = hx0 + x0;
            ky[k] = hy0 + y0;
        }
        __syncthreads();

        if (tid < KTOP){
            int k = tid;
            float px = kx[k], py = ky[k];
            float bsq = FLT_MAX; int bm = 0;
            #pragma unroll 4
            for (int mm = 0; mm < 100; mm++){
                float dx = px - hmx[mm];
                float dy = py - hmy[mm];
                float sq = dx*dx + dy*dy;
                if (sq < bsq){ bsq = sq; bm = mm; }
            }
            float smin = sqrtf(bsq);
            float lim = bsq * 1.000001f;   // sqrt rounding collapse window
            for (int mm = 0; mm < bm; mm++){
                float dx = px - hmx[mm];
                float dy = py - hmy[mm];
                float sq = dx*dx + dy*dy;
                if (sq <= lim && sqrtf(sq) == smin){ bm = mm; break; }
            }
            float hs = hmsc[bm], hx = hmx[bm], hy = hmy[bm];
            float l = bl[k], tt = bt[k], r = br[k], bo = bbm[k];
            bool invalid = (hx < l) || (hx > r) || (hy < tt) || (hy > bo) ||
                           (hs < THRESH) ||
                           (smin > fmaxf(bo - tt, r - l)*0.3f);
            float fx = invalid ? px : hx;
            float fy = invalid ? py : hy;
            float* det = out + ((size_t)b2*KTOP + k)*45;
            det[5 + 2*j] = fx*4.0f;
            det[6 + 2*j] = fy*4.0f;
            det[26 + j]  = hs;
        }
    }

    // ---- counter reset for graph replays (last tail CTA cleans up) ----
    __syncthreads();
    if (tid == 0){
        unsigned d = atomicAdd(&g_done2, 1u);
        if (d == (unsigned)(NTAIL - 1)){
            g_done = 0u;
            __threadfence();
            atomicExch(&g_done2, 0u);
        }
    }
}

// =====================================================================
extern "C" void kernel_launch(void* const* d_in, const int* in_sizes, int n_in,
                              void* d_out, int out_size){
    const float* hm        = (const float*)d_in[0];
    const float* wh        = (const float*)d_in[1];
    const float* hps       = (const float*)d_in[2];
    const float* dim       = (const float*)d_in[3];
    const float* rot       = (const float*)d_in[4];
    const float* prob      = (const float*)d_in[5];
    const float* reg       = (const float*)d_in[6];
    const float* hm_hp     = (const float*)d_in[7];
    const float* hp_offset = (const float*)d_in[8];
    float* out = (float*)d_out;

    const int SMEM1 = 45056 + 32768 + 4096 + 128;   // 82048 B
    cudaFuncSetAttribute(km3d_kernel,
                         cudaFuncAttributeMaxDynamicSharedMemorySize, SMEM1);

    km3d_kernel<<<BATCH*NMAPS, T1, SMEM1>>>(hm, hm_hp, wh, hps, dim, rot,
                                            prob, reg, hp_offset, out);
}